// round 4
// baseline (speedup 1.0000x reference)
#include <cuda_runtime.h>

#define BB 16
#define NTOK 2049
#define NK 2048
#define CC 1024
#define WS 3072

__device__ float g_qp[16 * BB * CC];   // q_cls partials: [dslice][b][c]
__device__ float g_qcls[BB * CC];
__device__ float g_v[BB * CC];
__device__ float g_psum[BB * 512];     // exp partial sums: [b][warp-partials]

// ---------------------------------------------------------------------------
// K1: q_cls partials. grid (8 c-tiles, 16 d-slices), 256 thr.
// Each block: all 16 batches, 128 c, 64 d. W_q read exactly once chip-wide.
// ---------------------------------------------------------------------------
__global__ __launch_bounds__(256) void k_qcls(const float* __restrict__ x,
                                              const float* __restrict__ w) {
    __shared__ float xs[16 * 64];        // [b][dd]
    __shared__ float red[4 * 16 * 128];  // [dg][b][c] 32KB
    const int t  = threadIdx.x;
    const int d0 = blockIdx.y * 64;
    const int c0 = blockIdx.x * 128;

    {
        const int b = t >> 4, dd = (t & 15) * 4;
        *(float4*)&xs[b * 64 + dd] =
            *(const float4*)&x[(size_t)b * NTOK * CC + d0 + dd];
    }
    __syncthreads();

    const int wid = t >> 5, lane = t & 31;
    const int dg = wid & 3, bg = wid >> 2;
    const int c = c0 + lane * 4;

    float4 a[8];
    #pragma unroll
    for (int j = 0; j < 8; j++) a[j] = make_float4(0.f, 0.f, 0.f, 0.f);

    const float* xb = &xs[bg * 8 * 64];
    #pragma unroll
    for (int i = 0; i < 16; i++) {
        const int dd = dg * 16 + i;
        const float4 w4 = *(const float4*)&w[(size_t)(d0 + dd) * WS + c];
        #pragma unroll
        for (int j = 0; j < 8; j++) {
            const float xv = xb[j * 64 + dd];
            a[j].x = fmaf(w4.x, xv, a[j].x);
            a[j].y = fmaf(w4.y, xv, a[j].y);
            a[j].z = fmaf(w4.z, xv, a[j].z);
            a[j].w = fmaf(w4.w, xv, a[j].w);
        }
    }
    #pragma unroll
    for (int j = 0; j < 8; j++)
        *(float4*)&red[dg * 2048 + (bg * 8 + j) * 128 + lane * 4] = a[j];
    __syncthreads();

    #pragma unroll
    for (int k = 0; k < 8; k++) {
        const int idx = t + 256 * k;
        const float s = (red[idx] + red[idx + 2048])
                      + (red[idx + 4096] + red[idx + 6144]);
        g_qp[(blockIdx.y * 16 + (idx >> 7)) * CC + c0 + (idx & 127)] = s;
    }
}

// ---------------------------------------------------------------------------
// K1b: collapse 16 d-slice partials -> g_qcls. grid (8,16), 128 thr.
// ---------------------------------------------------------------------------
__global__ __launch_bounds__(128) void k_qred() {
    const int b = blockIdx.y;
    const int c = blockIdx.x * 128 + threadIdx.x;
    float s = 0.f;
    #pragma unroll
    for (int ds = 0; ds < 16; ds++) s += g_qp[(ds * 16 + b) * CC + c];
    g_qcls[b * CC + c] = s;
}

// ---------------------------------------------------------------------------
// K2: v[b,d] = W_k[d,:] . q_cls[b,:]
// grid (128 d-blocks, 2 b-groups), 256 thr, warp per d, 8 batches/warp.
// ---------------------------------------------------------------------------
__global__ __launch_bounds__(256) void k_v(const float* __restrict__ w) {
    __shared__ float qs[8 * CC];
    const int bg   = blockIdx.y;
    const int d    = blockIdx.x * 8 + (threadIdx.x >> 5);
    const int lane = threadIdx.x & 31;

    #pragma unroll
    for (int i = 0; i < 8; i++)
        ((float4*)qs)[threadIdx.x + 256 * i] =
            ((const float4*)(g_qcls + bg * 8 * CC))[threadIdx.x + 256 * i];
    __syncthreads();

    const float* wr = w + (size_t)d * WS + CC;
    float acc[8];
    #pragma unroll
    for (int b = 0; b < 8; b++) acc[b] = 0.f;

    #pragma unroll
    for (int i = 0; i < 8; i++) {
        const int cc = i * 128 + lane * 4;
        const float4 w4 = *(const float4*)&wr[cc];
        #pragma unroll
        for (int b = 0; b < 8; b++) {
            const float4 q4 = *(const float4*)&qs[b * CC + cc];
            acc[b] = fmaf(w4.x, q4.x, acc[b]);
            acc[b] = fmaf(w4.y, q4.y, acc[b]);
            acc[b] = fmaf(w4.z, q4.z, acc[b]);
            acc[b] = fmaf(w4.w, q4.w, acc[b]);
        }
    }
    #pragma unroll
    for (int b = 0; b < 8; b++) {
        float a = acc[b];
        #pragma unroll
        for (int o = 16; o; o >>= 1) a += __shfl_xor_sync(0xffffffffu, a, o);
        if (lane == 0) g_v[(bg * 8 + b) * CC + d] = a;
    }
}

// ---------------------------------------------------------------------------
// K3 (dominant, HBM-bound): out[b,n] = exp(scale * x[b,n+1,:].v[b,:])
// 8 warps x 4 rows = 32 rows/block; grid (64, 16). 4 front-batched LDG.128
// per thread per iteration for MLP; v cached in smem, reused across 4 rows.
// Per-warp exp-sums go straight to g_psum.
// ---------------------------------------------------------------------------
__global__ __launch_bounds__(256, 4) void k_logits(const float* __restrict__ x,
                                                   float* __restrict__ out) {
    __shared__ float vs[CC];
    const int b = blockIdx.y;
    ((float4*)vs)[threadIdx.x] = ((const float4*)(g_v + b * CC))[threadIdx.x];
    __syncthreads();

    const int warp = threadIdx.x >> 5;
    const int lane = threadIdx.x & 31;
    const int n0 = (blockIdx.x * 8 + warp) * 4;              // 4 consecutive n
    const float4* xr = (const float4*)(x + ((size_t)b * NTOK + n0 + 1) * CC) + lane;

    float4 a0 = make_float4(0.f, 0.f, 0.f, 0.f);
    float4 a1 = a0, a2 = a0, a3 = a0;

    #pragma unroll
    for (int i = 0; i < 8; i++) {
        const int off = i * 32;
        const float4 r0 = __ldcs(xr + off);           // row n0
        const float4 r1 = __ldcs(xr + 256 + off);     // row n0+1
        const float4 r2 = __ldcs(xr + 512 + off);     // row n0+2
        const float4 r3 = __ldcs(xr + 768 + off);     // row n0+3
        const float4 vv = ((const float4*)vs)[off + lane];
        a0.x = fmaf(r0.x, vv.x, a0.x); a0.y = fmaf(r0.y, vv.y, a0.y);
        a0.z = fmaf(r0.z, vv.z, a0.z); a0.w = fmaf(r0.w, vv.w, a0.w);
        a1.x = fmaf(r1.x, vv.x, a1.x); a1.y = fmaf(r1.y, vv.y, a1.y);
        a1.z = fmaf(r1.z, vv.z, a1.z); a1.w = fmaf(r1.w, vv.w, a1.w);
        a2.x = fmaf(r2.x, vv.x, a2.x); a2.y = fmaf(r2.y, vv.y, a2.y);
        a2.z = fmaf(r2.z, vv.z, a2.z); a2.w = fmaf(r2.w, vv.w, a2.w);
        a3.x = fmaf(r3.x, vv.x, a3.x); a3.y = fmaf(r3.y, vv.y, a3.y);
        a3.z = fmaf(r3.z, vv.z, a3.z); a3.w = fmaf(r3.w, vv.w, a3.w);
    }
    float s0 = (a0.x + a0.y) + (a0.z + a0.w);
    float s1 = (a1.x + a1.y) + (a1.z + a1.w);
    float s2 = (a2.x + a2.y) + (a2.z + a2.w);
    float s3 = (a3.x + a3.y) + (a3.z + a3.w);
    #pragma unroll
    for (int o = 16; o; o >>= 1) {
        s0 += __shfl_xor_sync(0xffffffffu, s0, o);
        s1 += __shfl_xor_sync(0xffffffffu, s1, o);
        s2 += __shfl_xor_sync(0xffffffffu, s2, o);
        s3 += __shfl_xor_sync(0xffffffffu, s3, o);
    }
    if (lane == 0) {
        float4 e;
        e.x = __expf(s0 * 0.03125f);
        e.y = __expf(s1 * 0.03125f);
        e.z = __expf(s2 * 0.03125f);
        e.w = __expf(s3 * 0.03125f);
        *(float4*)&out[(b << 11) + n0] = e;
        g_psum[b * 512 + blockIdx.x * 8 + warp] = (e.x + e.y) + (e.z + e.w);
    }
}

// ---------------------------------------------------------------------------
// K4: normalize. grid (4 chunks, 16 b), 512 thr. Deterministic reduce of the
// 512 per-warp partials, then scale 512 elements each.
// ---------------------------------------------------------------------------
__global__ __launch_bounds__(512) void k_norm(float* __restrict__ out) {
    __shared__ float sp[512];
    const int b = blockIdx.y, t = threadIdx.x;
    sp[t] = g_psum[b * 512 + t];
    __syncthreads();
    #pragma unroll
    for (int o = 256; o; o >>= 1) {
        if (t < o) sp[t] += sp[t + o];
        __syncthreads();
    }
    const float inv = 1.0f / sp[0];
    const int idx = blockIdx.x * 512 + t;
    out[(b << 11) + idx] *= inv;
}

// ---------------------------------------------------------------------------
extern "C" void kernel_launch(void* const* d_in, const int* in_sizes, int n_in,
                              void* d_out, int out_size) {
    const float* x = (const float*)d_in[0];
    const float* w = (const float*)d_in[1];
    if (n_in >= 2 && in_sizes[0] == CC * WS && in_sizes[1] == BB * NTOK * CC) {
        x = (const float*)d_in[1];
        w = (const float*)d_in[0];
    }
    float* out = (float*)d_out;

    k_qcls  <<<dim3(8, 16),   256>>>(x, w);
    k_qred  <<<dim3(8, 16),   128>>>();
    k_v     <<<dim3(128, 2),  256>>>(w);
    k_logits<<<dim3(64, 16),  256>>>(x, out);
    k_norm  <<<dim3(4, 16),   512>>>(out);
}

// round 5
// speedup vs baseline: 1.1174x; 1.1174x over previous
#include <cuda_runtime.h>

#define BB 16
#define NTOK 2049
#define NK 2048
#define CC 1024
#define WS 3072

__device__ float g_qp[16 * BB * CC];   // q_cls partials: [dslice][b][c]
__device__ float g_qcls[BB * CC];
__device__ float g_v[BB * CC];
__device__ float g_psum[BB * 512];     // exp partial sums: [b][warp]

// ---------------------------------------------------------------------------
// K1: q_cls partials. grid (8 c-tiles, 16 d-slices), 256 thr.
// W_q read exactly once chip-wide.
// ---------------------------------------------------------------------------
__global__ __launch_bounds__(256) void k_qcls(const float* __restrict__ x,
                                              const float* __restrict__ w) {
    __shared__ float xs[16 * 64];
    __shared__ float red[4 * 16 * 128];
    const int t  = threadIdx.x;
    const int d0 = blockIdx.y * 64;
    const int c0 = blockIdx.x * 128;

    {
        const int b = t >> 4, dd = (t & 15) * 4;
        *(float4*)&xs[b * 64 + dd] =
            *(const float4*)&x[(size_t)b * NTOK * CC + d0 + dd];
    }
    __syncthreads();

    const int wid = t >> 5, lane = t & 31;
    const int dg = wid & 3, bg = wid >> 2;
    const int c = c0 + lane * 4;

    float4 a[8];
    #pragma unroll
    for (int j = 0; j < 8; j++) a[j] = make_float4(0.f, 0.f, 0.f, 0.f);

    const float* xb = &xs[bg * 8 * 64];
    #pragma unroll
    for (int i = 0; i < 16; i++) {
        const int dd = dg * 16 + i;
        const float4 w4 = *(const float4*)&w[(size_t)(d0 + dd) * WS + c];
        #pragma unroll
        for (int j = 0; j < 8; j++) {
            const float xv = xb[j * 64 + dd];
            a[j].x = fmaf(w4.x, xv, a[j].x);
            a[j].y = fmaf(w4.y, xv, a[j].y);
            a[j].z = fmaf(w4.z, xv, a[j].z);
            a[j].w = fmaf(w4.w, xv, a[j].w);
        }
    }
    #pragma unroll
    for (int j = 0; j < 8; j++)
        *(float4*)&red[dg * 2048 + (bg * 8 + j) * 128 + lane * 4] = a[j];
    __syncthreads();

    #pragma unroll
    for (int k = 0; k < 8; k++) {
        const int idx = t + 256 * k;
        const float s = (red[idx] + red[idx + 2048])
                      + (red[idx + 4096] + red[idx + 6144]);
        g_qp[(blockIdx.y * 16 + (idx >> 7)) * CC + c0 + (idx & 127)] = s;
    }
}

// ---------------------------------------------------------------------------
// K1b: collapse 16 d-slice partials. grid (8,16), 128 thr.
// ---------------------------------------------------------------------------
__global__ __launch_bounds__(128) void k_qred() {
    const int b = blockIdx.y;
    const int c = blockIdx.x * 128 + threadIdx.x;
    float s = 0.f;
    #pragma unroll
    for (int ds = 0; ds < 16; ds++) s += g_qp[(ds * 16 + b) * CC + c];
    g_qcls[b * CC + c] = s;
}

// ---------------------------------------------------------------------------
// K2: v[b,d] = W_k[d,:] . q_cls[b,:]
// grid (128, 2), 256 thr, warp per d, 8 batches/warp.
// ---------------------------------------------------------------------------
__global__ __launch_bounds__(256) void k_v(const float* __restrict__ w) {
    __shared__ float qs[8 * CC];
    const int bg   = blockIdx.y;
    const int d    = blockIdx.x * 8 + (threadIdx.x >> 5);
    const int lane = threadIdx.x & 31;

    #pragma unroll
    for (int i = 0; i < 8; i++)
        ((float4*)qs)[threadIdx.x + 256 * i] =
            ((const float4*)(g_qcls + bg * 8 * CC))[threadIdx.x + 256 * i];
    __syncthreads();

    const float* wr = w + (size_t)d * WS + CC;
    float acc[8];
    #pragma unroll
    for (int b = 0; b < 8; b++) acc[b] = 0.f;

    #pragma unroll
    for (int i = 0; i < 8; i++) {
        const int cc = i * 128 + lane * 4;
        const float4 w4 = *(const float4*)&wr[cc];
        #pragma unroll
        for (int b = 0; b < 8; b++) {
            const float4 q4 = *(const float4*)&qs[b * CC + cc];
            acc[b] = fmaf(w4.x, q4.x, acc[b]);
            acc[b] = fmaf(w4.y, q4.y, acc[b]);
            acc[b] = fmaf(w4.z, q4.z, acc[b]);
            acc[b] = fmaf(w4.w, q4.w, acc[b]);
        }
    }
    #pragma unroll
    for (int b = 0; b < 8; b++) {
        float a = acc[b];
        #pragma unroll
        for (int o = 16; o; o >>= 1) a += __shfl_xor_sync(0xffffffffu, a, o);
        if (lane == 0) g_v[(bg * 8 + b) * CC + d] = a;
    }
}

// ---------------------------------------------------------------------------
// K3 (dominant, HBM-bound): out[b,n] = exp(scale * x[b,n+1,:].v[b,:])
// grid (64, 16) = 1024 blocks -> single wave at 8 blocks/SM. 256 thr.
// Each warp: 2 passes x 2 rows (R3 inner shape: 2 LDG.128/iter, 32 regs).
// Per-warp exp partial -> g_psum.
// ---------------------------------------------------------------------------
__global__ __launch_bounds__(256) void k_logits(const float* __restrict__ x,
                                                float* __restrict__ out) {
    __shared__ float vs[CC];
    const int b = blockIdx.y;
    ((float4*)vs)[threadIdx.x] = ((const float4*)(g_v + b * CC))[threadIdx.x];
    __syncthreads();

    const int warp = threadIdx.x >> 5;
    const int lane = threadIdx.x & 31;
    float psum = 0.f;

    #pragma unroll
    for (int p = 0; p < 2; p++) {
        const int n0 = blockIdx.x * 32 + p * 16 + warp * 2;
        const float4* x0 = (const float4*)(x + ((size_t)b * NTOK + n0 + 1) * CC) + lane;

        float4 a0 = make_float4(0.f, 0.f, 0.f, 0.f);
        float4 a1 = a0;
        #pragma unroll
        for (int i = 0; i < 8; i++) {
            const int off = i * 32;
            const float4 xv0 = __ldcs(x0 + off);
            const float4 xv1 = __ldcs(x0 + 256 + off);
            const float4 vv  = ((const float4*)vs)[off + lane];
            a0.x = fmaf(xv0.x, vv.x, a0.x); a0.y = fmaf(xv0.y, vv.y, a0.y);
            a0.z = fmaf(xv0.z, vv.z, a0.z); a0.w = fmaf(xv0.w, vv.w, a0.w);
            a1.x = fmaf(xv1.x, vv.x, a1.x); a1.y = fmaf(xv1.y, vv.y, a1.y);
            a1.z = fmaf(xv1.z, vv.z, a1.z); a1.w = fmaf(xv1.w, vv.w, a1.w);
        }
        float s0 = (a0.x + a0.y) + (a0.z + a0.w);
        float s1 = (a1.x + a1.y) + (a1.z + a1.w);
        #pragma unroll
        for (int o = 16; o; o >>= 1) {
            s0 += __shfl_xor_sync(0xffffffffu, s0, o);
            s1 += __shfl_xor_sync(0xffffffffu, s1, o);
        }
        if (lane == 0) {
            float2 e;
            e.x = __expf(s0 * 0.03125f);
            e.y = __expf(s1 * 0.03125f);
            *(float2*)&out[(b << 11) + n0] = e;
            psum += e.x + e.y;
        }
    }
    if (lane == 0)
        g_psum[b * 512 + blockIdx.x * 8 + warp] = psum;
}

// ---------------------------------------------------------------------------
// K4: normalize. grid (4, 16), 512 thr.
// ---------------------------------------------------------------------------
__global__ __launch_bounds__(512) void k_norm(float* __restrict__ out) {
    __shared__ float sp[512];
    const int b = blockIdx.y, t = threadIdx.x;
    sp[t] = g_psum[b * 512 + t];
    __syncthreads();
    #pragma unroll
    for (int o = 256; o; o >>= 1) {
        if (t < o) sp[t] += sp[t + o];
        __syncthreads();
    }
    const float inv = 1.0f / sp[0];
    const int idx = blockIdx.x * 512 + t;
    out[(b << 11) + idx] *= inv;
}

// ---------------------------------------------------------------------------
extern "C" void kernel_launch(void* const* d_in, const int* in_sizes, int n_in,
                              void* d_out, int out_size) {
    const float* x = (const float*)d_in[0];
    const float* w = (const float*)d_in[1];
    if (n_in >= 2 && in_sizes[0] == CC * WS && in_sizes[1] == BB * NTOK * CC) {
        x = (const float*)d_in[1];
        w = (const float*)d_in[0];
    }
    float* out = (float*)d_out;

    k_qcls  <<<dim3(8, 16),   256>>>(x, w);
    k_qred  <<<dim3(8, 16),   128>>>();
    k_v     <<<dim3(128, 2),  256>>>(w);
    k_logits<<<dim3(64, 16),  256>>>(x, out);
    k_norm  <<<dim3(4, 16),   512>>>(out);
}